// round 1
// baseline (speedup 1.0000x reference)
#include <cuda_runtime.h>
#include <math.h>

// Problem constants (fixed for this problem instance)
#define BB   8      // batch
#define LL   2048   // sequence length
#define HH   1024   // hidden
#define TT   256    // max_length (table cells)
#define M1   (BB * LL)   // 16384 rows for GEMM1
#define M2   (BB * TT)   // 2048 rows for GEMM2

// Scratch (allocation-free rule: __device__ globals)
__device__ float g_seq[(size_t)M1 * HH];     // gelu(concat(x) @ W_down + b)   64 MiB
__device__ float g_cell1[(size_t)M2 * HH];   // segment sums                    8 MiB
__device__ float g_cell2[(size_t)M2 * HH];   // gelu(cell1 @ W_row + b)         8 MiB

__device__ __forceinline__ float gelu_exact(float x) {
    // exact erf-based gelu, matching jax.nn.gelu(approximate=False)
    return 0.5f * x * (1.0f + erff(x * 0.7071067811865475244f));
}

// ---------------------------------------------------------------------------
// GEMM + bias + gelu.
// C[M, N] = gelu( X[M, K] @ W[K, N] + bias[N] )
// X is logically the concat of A0 (cols [0, Ksplit)) and A1 (cols [Ksplit, K)).
// For GEMM2, Ksplit == K so A1 is never touched.
// Tiling: 128x128x8 block tile, 256 threads, 8x8 register tile per thread.
// ---------------------------------------------------------------------------
__global__ void __launch_bounds__(256, 2)
gemm_bias_gelu(const float* __restrict__ A0, const float* __restrict__ A1,
               int Ksplit, int K,
               const float* __restrict__ Wm, const float* __restrict__ bias,
               float* __restrict__ C)
{
    constexpr int BM = 128, BN = 128, BK = 8;
    constexpr int N = HH;

    __shared__ float As[BK][BM];   // A stored transposed: As[k][m]
    __shared__ float Bs[BK][BN];

    const int tid = threadIdx.x;
    const int tx = tid & 15;    // -> n direction (0..15)
    const int ty = tid >> 4;    // -> m direction (0..15)
    const int mBase = blockIdx.y * BM;
    const int nBase = blockIdx.x * BN;

    // A tile load mapping: 128 rows x 8 k, each thread one float4
    const int a_row = tid >> 1;          // 0..127
    const int a_k   = (tid & 1) * 4;     // 0 or 4
    // B tile load mapping: 8 k x 128 n, each thread one float4
    const int b_k = tid >> 5;            // 0..7
    const int b_n = (tid & 31) * 4;      // 0..124

    const int strideA1 = K - Ksplit;

    float acc[8][8];
    #pragma unroll
    for (int i = 0; i < 8; i++)
        #pragma unroll
        for (int j = 0; j < 8; j++)
            acc[i][j] = 0.0f;

    for (int k0 = 0; k0 < K; k0 += BK) {
        // ---- load A tile (concat-aware; BK=8 never straddles Ksplit since Ksplit%8==0)
        {
            const int kg = k0 + a_k;
            const float* src;
            if (kg < Ksplit)
                src = A0 + (size_t)(mBase + a_row) * Ksplit + kg;
            else
                src = A1 + (size_t)(mBase + a_row) * strideA1 + (kg - Ksplit);
            const float4 av = *reinterpret_cast<const float4*>(src);
            As[a_k + 0][a_row] = av.x;
            As[a_k + 1][a_row] = av.y;
            As[a_k + 2][a_row] = av.z;
            As[a_k + 3][a_row] = av.w;
        }
        // ---- load B tile
        {
            const float4 bv = *reinterpret_cast<const float4*>(
                Wm + (size_t)(k0 + b_k) * N + (nBase + b_n));
            *reinterpret_cast<float4*>(&Bs[b_k][b_n]) = bv;
        }
        __syncthreads();

        #pragma unroll
        for (int k = 0; k < BK; k++) {
            float a[8], b[8];
            *reinterpret_cast<float4*>(&a[0]) = *reinterpret_cast<const float4*>(&As[k][ty * 8 + 0]);
            *reinterpret_cast<float4*>(&a[4]) = *reinterpret_cast<const float4*>(&As[k][ty * 8 + 4]);
            *reinterpret_cast<float4*>(&b[0]) = *reinterpret_cast<const float4*>(&Bs[k][tx * 8 + 0]);
            *reinterpret_cast<float4*>(&b[4]) = *reinterpret_cast<const float4*>(&Bs[k][tx * 8 + 4]);
            #pragma unroll
            for (int i = 0; i < 8; i++)
                #pragma unroll
                for (int j = 0; j < 8; j++)
                    acc[i][j] = fmaf(a[i], b[j], acc[i][j]);
        }
        __syncthreads();
    }

    // ---- epilogue: bias + gelu, vectorized stores
    #pragma unroll
    for (int i = 0; i < 8; i++) {
        const int m = mBase + ty * 8 + i;
        #pragma unroll
        for (int j = 0; j < 8; j += 4) {
            const int n = nBase + tx * 8 + j;
            float4 o;
            o.x = gelu_exact(acc[i][j + 0] + bias[n + 0]);
            o.y = gelu_exact(acc[i][j + 1] + bias[n + 1]);
            o.z = gelu_exact(acc[i][j + 2] + bias[n + 2]);
            o.w = gelu_exact(acc[i][j + 3] + bias[n + 3]);
            *reinterpret_cast<float4*>(&C[(size_t)m * N + n]) = o;
        }
    }
}

// ---------------------------------------------------------------------------
// Deterministic segment sum:
//   g_cell1[b, t, :] = sum over l with ids[b,l]==t of g_seq[b*L + l, :]
// One block per (t, b): 256 threads x float4 covers H=1024.
// L-loop is sequential -> bitwise deterministic (no float atomics).
// ---------------------------------------------------------------------------
__global__ void __launch_bounds__(256)
segsum_kernel(const int* __restrict__ ids)
{
    __shared__ int s_ids[LL];
    const int t = blockIdx.x;
    const int b = blockIdx.y;
    const int tid = threadIdx.x;

    for (int i = tid; i < LL; i += 256)
        s_ids[i] = ids[b * LL + i];
    __syncthreads();

    float4 acc = make_float4(0.f, 0.f, 0.f, 0.f);
    const float4* base = reinterpret_cast<const float4*>(g_seq) + (size_t)b * LL * (HH / 4) + tid;

    for (int l = 0; l < LL; l++) {
        if (s_ids[l] == t) {
            const float4 v = base[(size_t)l * (HH / 4)];
            acc.x += v.x; acc.y += v.y; acc.z += v.z; acc.w += v.w;
        }
    }

    reinterpret_cast<float4*>(g_cell1)[((size_t)(b * TT + t)) * (HH / 4) + tid] = acc;
}

// ---------------------------------------------------------------------------
// Gather: out[b, l, :] = g_cell2[b, ids[b,l], :]
// ---------------------------------------------------------------------------
__global__ void __launch_bounds__(256)
gather_kernel(const int* __restrict__ ids, float* __restrict__ out)
{
    const int l = blockIdx.x;
    const int b = blockIdx.y;
    const int tid = threadIdx.x;
    const int t = ids[b * LL + l];

    const float4 v = reinterpret_cast<const float4*>(g_cell2)[((size_t)(b * TT + t)) * (HH / 4) + tid];
    reinterpret_cast<float4*>(out)[((size_t)(b * LL + l)) * (HH / 4) + tid] = v;
}

extern "C" void kernel_launch(void* const* d_in, const int* in_sizes, int n_in,
                              void* d_out, int out_size)
{
    const float* former = (const float*)d_in[0];   // [8, 2048, 1024]
    const float* hidden = (const float*)d_in[1];   // [8, 2048, 1024]
    const int*   ids    = (const int*)  d_in[2];   // [8, 2048]
    // d_in[3] attention_mask: unused by reference
    const float* Wd     = (const float*)d_in[4];   // [2048, 1024]
    const float* bd     = (const float*)d_in[5];   // [1024]
    const float* Wr     = (const float*)d_in[6];   // [1024, 1024]
    const float* br     = (const float*)d_in[7];   // [1024]
    // d_in[8] max_length scalar: fixed at 256
    float* out = (float*)d_out;

    float *seq, *c1, *c2;
    cudaGetSymbolAddress((void**)&seq, g_seq);
    cudaGetSymbolAddress((void**)&c1, g_cell1);
    cudaGetSymbolAddress((void**)&c2, g_cell2);

    // Stage 1: seq = gelu(concat(former, hidden) @ W_down + b_down)
    gemm_bias_gelu<<<dim3(HH / 128, M1 / 128), 256>>>(
        former, hidden, /*Ksplit=*/HH, /*K=*/2 * HH, Wd, bd, seq);

    // Stage 2: deterministic segment sum into table cells
    segsum_kernel<<<dim3(TT, BB), 256>>>(ids);

    // Stage 3: cell2 = gelu(cell1 @ W_row + b_row)
    gemm_bias_gelu<<<dim3(HH / 128, M2 / 128), 256>>>(
        c1, c1, /*Ksplit=*/HH, /*K=*/HH, Wr, br, c2);

    // Stage 4: gather cells back to token positions
    gather_kernel<<<dim3(LL, BB), 256>>>(ids, out);
}

// round 8
// speedup vs baseline: 3.5014x; 3.5014x over previous
#include <cuda_runtime.h>
#include <cuda_bf16.h>
#include <math.h>
#include <stdint.h>

#define BB   8
#define LL   2048
#define HH   1024
#define TT   256
#define M1   (BB * LL)    // 16384
#define M2   (BB * TT)    // 2048

// tcgen05 is only legal when compiling an arch-specific target (sm_103a/sm_100a).
// The bench's PTX pass targets base sm_103, where tcgen05 does not exist — that
// pass must compile the mma.sync fallback instead.
#if defined(__CUDA_ARCH_FEAT_SM103_ALL) || defined(__CUDA_ARCH_FEAT_SM100_ALL) || \
    (defined(__CUDA_ARCH_SPECIFIC__) && (__CUDA_ARCH_SPECIFIC__ >= 1000))
#define HAS_TCGEN05 1
#else
#define HAS_TCGEN05 0
#endif

// ---------------- scratch (__device__ globals; no allocation allowed) -------
__device__ float g_seq[(size_t)M1 * HH];      // 64 MiB
__device__ float g_cell1[(size_t)M2 * HH];    //  8 MiB
__device__ float g_cell2[(size_t)M2 * HH];    //  8 MiB
__device__ __align__(16) __nv_bfloat16 g_WdT_hi[(size_t)HH * 2 * HH];  // [1024][2048]
__device__ __align__(16) __nv_bfloat16 g_WdT_lo[(size_t)HH * 2 * HH];
__device__ __align__(16) __nv_bfloat16 g_WrT_hi[(size_t)HH * HH];      // [1024][1024]
__device__ __align__(16) __nv_bfloat16 g_WrT_lo[(size_t)HH * HH];

// ---------------- shared helpers --------------------------------------------
__device__ __forceinline__ uint32_t pk_bf(__nv_bfloat16 a, __nv_bfloat16 b) {
    return (uint32_t)__bfloat16_as_ushort(a) | ((uint32_t)__bfloat16_as_ushort(b) << 16);
}
__device__ __forceinline__ float gelu_exact(float x) {
    return 0.5f * x * (1.0f + erff(x * 0.7071067811865475244f));
}

#if HAS_TCGEN05
// ---------------- tcgen05 helpers (arch-specific pass only) -----------------
__device__ __forceinline__ uint32_t smem_u32(const void* p) {
    uint32_t a;
    asm("{ .reg .u64 t; cvta.to.shared.u64 t, %1; cvt.u32.u64 %0, t; }" : "=r"(a) : "l"(p));
    return a;
}
__device__ __forceinline__ uint32_t elect1() {
    uint32_t r;
    asm volatile("{ .reg .pred p; elect.sync _|p, 0xFFFFFFFF; selp.b32 %0, 1, 0, p; }" : "=r"(r));
    return r;
}
__device__ __forceinline__ void mbar_init(uint32_t a, uint32_t cnt) {
    asm volatile("mbarrier.init.shared.b64 [%0], %1;" :: "r"(a), "r"(cnt) : "memory");
}
__device__ __forceinline__ void mbar_wait(uint32_t a, uint32_t phase) {
    uint32_t done;
    asm volatile(
        "{\n\t.reg .pred p;\n\t"
        "mbarrier.try_wait.parity.acquire.cta.shared::cta.b64 p, [%1], %2;\n\t"
        "selp.b32 %0, 1, 0, p;\n\t}"
        : "=r"(done) : "r"(a), "r"(phase) : "memory");
    if (!done) {
        asm volatile(
            "{\n\t.reg .pred P1;\n\t"
            "WL_%=:\n\t"
            "mbarrier.try_wait.parity.acquire.cta.shared::cta.b64 P1, [%0], %1, 0x989680;\n\t"
            "@P1 bra.uni WD_%=;\n\t"
            "bra.uni WL_%=;\n\t"
            "WD_%=:\n\t}"
            :: "r"(a), "r"(phase) : "memory");
    }
}
__device__ __forceinline__ void tmem_alloc(uint32_t smem_dst, uint32_t ncols) {
    asm volatile("tcgen05.alloc.cta_group::1.sync.aligned.shared::cta.b32 [%0], %1;"
                 :: "r"(smem_dst), "r"(ncols) : "memory");
}
__device__ __forceinline__ void tmem_dealloc(uint32_t tmem, uint32_t ncols) {
    asm volatile("tcgen05.relinquish_alloc_permit.cta_group::1.sync.aligned;");
    asm volatile("tcgen05.dealloc.cta_group::1.sync.aligned.b32 %0, %1;" :: "r"(tmem), "r"(ncols));
}
__device__ __forceinline__ void tc_commit(uint32_t mbar) {
    asm volatile("tcgen05.commit.cta_group::1.mbarrier::arrive::one.shared::cluster.b64 [%0];"
                 :: "r"(mbar) : "memory");
}
__device__ __forceinline__ void fence_async_shared() {
    asm volatile("fence.proxy.async.shared::cta;" ::: "memory");
}
__device__ __forceinline__ void tc_fence_after() {
    asm volatile("tcgen05.fence::after_thread_sync;" ::: "memory");
}
__device__ __forceinline__ void mma_f16_ss(uint32_t d, uint64_t ad, uint64_t bd,
                                           uint32_t idesc, uint32_t en) {
    asm volatile(
        "{\n\t.reg .pred p;\n\tsetp.ne.u32 p, %4, 0;\n\t"
        "tcgen05.mma.cta_group::1.kind::f16 [%0], %1, %2, %3, {%5, %5, %5, %5}, p;\n\t}"
        :: "r"(d), "l"(ad), "l"(bd), "r"(idesc), "r"(en), "r"(0u) : "memory");
}
#define LDTM_X32(r, addr)                                                         \
    asm volatile("tcgen05.ld.sync.aligned.32x32b.x32.b32 "                        \
        "{%0,%1,%2,%3,%4,%5,%6,%7,%8,%9,%10,%11,%12,%13,%14,%15,"                 \
        "%16,%17,%18,%19,%20,%21,%22,%23,%24,%25,%26,%27,%28,%29,%30,%31}, [%32];"\
        : "=r"((r)[0]),"=r"((r)[1]),"=r"((r)[2]),"=r"((r)[3]),                    \
          "=r"((r)[4]),"=r"((r)[5]),"=r"((r)[6]),"=r"((r)[7]),                    \
          "=r"((r)[8]),"=r"((r)[9]),"=r"((r)[10]),"=r"((r)[11]),                  \
          "=r"((r)[12]),"=r"((r)[13]),"=r"((r)[14]),"=r"((r)[15]),                \
          "=r"((r)[16]),"=r"((r)[17]),"=r"((r)[18]),"=r"((r)[19]),                \
          "=r"((r)[20]),"=r"((r)[21]),"=r"((r)[22]),"=r"((r)[23]),                \
          "=r"((r)[24]),"=r"((r)[25]),"=r"((r)[26]),"=r"((r)[27]),                \
          "=r"((r)[28]),"=r"((r)[29]),"=r"((r)[30]),"=r"((r)[31])                 \
        : "r"(addr))
__device__ __forceinline__ void ldtm_wait() {
    asm volatile("tcgen05.wait::ld.sync.aligned;" ::: "memory");
}
__device__ __forceinline__ uint64_t make_desc_sw128(uint32_t addr) {
    const uint64_t base = (uint64_t(2) << 61) | (uint64_t(1) << 46) |
                          (uint64_t(64) << 32) | (uint64_t(1) << 16);
    return base | ((uint64_t)(addr >> 4) & 0x3FFF);
}
#define IDESC_BF16_M128_N128 0x08200490u
#else
// ---------------- fallback helper: classic bf16 tensor-core mma -------------
__device__ __forceinline__ void mma_bf16_16816(float* c, const uint32_t* a,
                                               uint32_t b0, uint32_t b1) {
    asm volatile(
        "mma.sync.aligned.m16n8k16.row.col.f32.bf16.bf16.f32 "
        "{%0,%1,%2,%3}, {%4,%5,%6,%7}, {%8,%9}, {%0,%1,%2,%3};"
        : "+f"(c[0]), "+f"(c[1]), "+f"(c[2]), "+f"(c[3])
        : "r"(a[0]), "r"(a[1]), "r"(a[2]), "r"(a[3]), "r"(b0), "r"(b1));
}
#endif

// ---------------------------------------------------------------------------
// W transpose + bf16 hi/lo split:  T[n][k] = split(W[k][n])
// ---------------------------------------------------------------------------
__global__ void __launch_bounds__(256)
wtrans(const float* __restrict__ W, int K, int N,
       __nv_bfloat16* __restrict__ Thi, __nv_bfloat16* __restrict__ Tlo)
{
    __shared__ float t[32][33];
    const int n0 = blockIdx.x * 32, k0 = blockIdx.y * 32;
    const int tx = threadIdx.x & 31, ty = threadIdx.x >> 5;
    #pragma unroll
    for (int i = ty; i < 32; i += 8)
        t[i][tx] = W[(size_t)(k0 + i) * N + n0 + tx];
    __syncthreads();
    #pragma unroll
    for (int i = ty; i < 32; i += 8) {
        float x = t[tx][i];
        __nv_bfloat16 h = __float2bfloat16_rn(x);
        __nv_bfloat16 l = __float2bfloat16_rn(x - __bfloat162float(h));
        size_t o = (size_t)(n0 + i) * K + k0 + tx;
        Thi[o] = h;
        Tlo[o] = l;
    }
}

// ---------------------------------------------------------------------------
// GEMM + bias + gelu:  C[m][n] = gelu( A[m][:] . Wt[n][:] + bias[n] )
// A fp32 (logical concat A0|A1 split at Ksplit), Wt bf16 hi/lo [N][K].
// CTA tile 256(M) x 128(N). Two implementations selected at compile time:
//   - tcgen05 pipeline (arch-specific pass)
//   - mma.sync.m16n8k16 bf16 fallback (base sm_103 pass)
// Both use the 3-term bf16 split: Ahi*Bhi + Alo*Bhi + Ahi*Blo.
// ---------------------------------------------------------------------------
#define STAGE_BYTES 98304
#define SMEM_TOTAL  (1024 + 1024 + 2 * STAGE_BYTES)

__global__ void __launch_bounds__(256, 1)
gemm_tc(const float* __restrict__ A0, const float* __restrict__ A1,
        int lda, int Ksplit, int K, int kchunks,
        const __nv_bfloat16* __restrict__ Whi, const __nv_bfloat16* __restrict__ Wlo,
        const float* __restrict__ bias, float* __restrict__ C)
{
#if HAS_TCGEN05
    extern __shared__ char smem_raw[];
    const uint32_t sbase = smem_u32(smem_raw);
    const uint32_t abase = (sbase + 1023u) & ~1023u;
    char* sm = smem_raw + (abase - sbase);

    const uint32_t tmem_ptr_a = abase;
    const uint32_t mbar[2]    = { abase + 8, abase + 16 };
    float* sBias              = (float*)(sm + 512);

    const int tid = threadIdx.x, wid = tid >> 5, lid = tid & 31;
    const int mBase = blockIdx.y * 256;
    const int nBase = blockIdx.x * 128;

    if (wid == 0) tmem_alloc(tmem_ptr_a, 256);
    if (tid == 0) { mbar_init(mbar[0], 1); mbar_init(mbar[1], 1); }
    if (tid < 128) sBias[tid] = bias[nBase + tid];
    __syncthreads();

    uint32_t tmem_base;
    asm volatile("ld.shared.b32 %0, [%1];" : "=r"(tmem_base) : "r"(tmem_ptr_a));

    const int aCol = tid & 15, aRow0 = tid >> 4;
    const int bCol = tid & 7,  bRow0 = tid >> 3;

    for (int s = 0; s < kchunks; s++) {
        const int slot = s & 1;
        if (s >= 2) mbar_wait(mbar[slot], ((s - 2) >> 1) & 1);

        char* st   = sm + 1024 + slot * STAGE_BYTES;
        char* sAhi = st;
        char* sAlo = st + 32768;
        char* sBhi = st + 65536;
        char* sBlo = st + 81920;
        const int k0 = s * 64;

        const float* aSrc = (k0 < Ksplit)
            ? (A0 + (size_t)mBase * lda + k0)
            : (A1 + (size_t)mBase * lda + (k0 - Ksplit));
        #pragma unroll
        for (int i = 0; i < 16; i++) {
            const int r = aRow0 + (i << 4);
            const float4 v = *(const float4*)(aSrc + (size_t)r * lda + (aCol << 2));
            __nv_bfloat16 h0 = __float2bfloat16_rn(v.x);
            __nv_bfloat16 h1 = __float2bfloat16_rn(v.y);
            __nv_bfloat16 h2 = __float2bfloat16_rn(v.z);
            __nv_bfloat16 h3 = __float2bfloat16_rn(v.w);
            __nv_bfloat16 l0 = __float2bfloat16_rn(v.x - __bfloat162float(h0));
            __nv_bfloat16 l1 = __float2bfloat16_rn(v.y - __bfloat162float(h1));
            __nv_bfloat16 l2 = __float2bfloat16_rn(v.z - __bfloat162float(h2));
            __nv_bfloat16 l3 = __float2bfloat16_rn(v.w - __bfloat162float(h3));
            uint32_t off = (r << 7) + (aCol << 3);
            uint32_t sw  = off ^ ((off >> 3) & 0x70);
            *(uint2*)(sAhi + sw) = make_uint2(pk_bf(h0, h1), pk_bf(h2, h3));
            *(uint2*)(sAlo + sw) = make_uint2(pk_bf(l0, l1), pk_bf(l2, l3));
        }
        const __nv_bfloat16* bh = Whi + (size_t)nBase * K + k0;
        const __nv_bfloat16* bl = Wlo + (size_t)nBase * K + k0;
        #pragma unroll
        for (int i = 0; i < 4; i++) {
            const int r = bRow0 + (i << 5);
            const uint4 vh = *(const uint4*)(bh + (size_t)r * K + (bCol << 3));
            const uint4 vl = *(const uint4*)(bl + (size_t)r * K + (bCol << 3));
            uint32_t off = (r << 7) + (bCol << 4);
            uint32_t sw  = off ^ ((off >> 3) & 0x70);
            *(uint4*)(sBhi + sw) = vh;
            *(uint4*)(sBlo + sw) = vl;
        }
        fence_async_shared();
        __syncthreads();

        if (wid == 0 && elect1()) {
            const uint32_t stU = abase + 1024 + slot * STAGE_BYTES;
            const uint64_t bdh = make_desc_sw128(stU + 65536);
            const uint64_t bdl = make_desc_sw128(stU + 81920);
            #pragma unroll
            for (int sub = 0; sub < 2; sub++) {
                const uint32_t d   = tmem_base + sub * 128;
                const uint64_t adh = make_desc_sw128(stU + sub * 16384);
                const uint64_t adl = make_desc_sw128(stU + 32768 + sub * 16384);
                #pragma unroll
                for (int ks = 0; ks < 4; ks++)
                    mma_f16_ss(d, adh + 2 * ks, bdh + 2 * ks, IDESC_BF16_M128_N128,
                               (s == 0 && ks == 0) ? 0u : 1u);
                #pragma unroll
                for (int ks = 0; ks < 4; ks++)
                    mma_f16_ss(d, adl + 2 * ks, bdh + 2 * ks, IDESC_BF16_M128_N128, 1u);
                #pragma unroll
                for (int ks = 0; ks < 4; ks++)
                    mma_f16_ss(d, adh + 2 * ks, bdl + 2 * ks, IDESC_BF16_M128_N128, 1u);
            }
            tc_commit(mbar[slot]);
        }
    }

    {
        const int s2 = kchunks - 2, s1 = kchunks - 1;
        mbar_wait(mbar[s2 & 1], (s2 >> 1) & 1);
        mbar_wait(mbar[s1 & 1], (s1 >> 1) & 1);
    }
    tc_fence_after();

    {
        const int wg = wid >> 2, wsub = wid & 3;
        const int m = mBase + wg * 128 + wsub * 32 + lid;
        const uint32_t dbase = tmem_base + wg * 128;
        #pragma unroll
        for (int cb = 0; cb < 4; cb++) {
            uint32_t regs[32];
            LDTM_X32(regs, dbase + cb * 32);
            ldtm_wait();
            float* crow = C + (size_t)m * HH + nBase + cb * 32;
            #pragma unroll
            for (int j = 0; j < 32; j += 4) {
                float4 o;
                o.x = gelu_exact(__uint_as_float(regs[j + 0]) + sBias[cb * 32 + j + 0]);
                o.y = gelu_exact(__uint_as_float(regs[j + 1]) + sBias[cb * 32 + j + 1]);
                o.z = gelu_exact(__uint_as_float(regs[j + 2]) + sBias[cb * 32 + j + 2]);
                o.w = gelu_exact(__uint_as_float(regs[j + 3]) + sBias[cb * 32 + j + 3]);
                *(float4*)(crow + j) = o;
            }
        }
    }
    __syncthreads();
    if (wid == 0) tmem_dealloc(tmem_base, 256);

#else  // ===================== mma.sync bf16 fallback =======================
    // SMEM: padded stride 72 bf16 (144 B) per row -> conflict-free fragment LDS.
    extern __shared__ char smem_raw[];
    float* sBias = (float*)(smem_raw + 512);
    char* sm = smem_raw + 1024;
    __nv_bfloat16* sAhi = (__nv_bfloat16*)(sm);              // 128 x 72 = 18432 B
    __nv_bfloat16* sAlo = (__nv_bfloat16*)(sm + 18432);
    __nv_bfloat16* sBhi = (__nv_bfloat16*)(sm + 36864);
    __nv_bfloat16* sBlo = (__nv_bfloat16*)(sm + 55296);

    const int tid = threadIdx.x, wid = tid >> 5, lane = tid & 31;
    const int mBase = blockIdx.y * 256;
    const int nBase = blockIdx.x * 128;
    const int g = lane >> 2, t = lane & 3;
    const int warpM = wid >> 1, warpN = wid & 1;     // 4 (M) x 2 (N) warps

    if (tid < 128) sBias[tid] = bias[nBase + tid];

    for (int half = 0; half < 2; half++) {
        const int mHalf = mBase + half * 128;
        float acc[2][8][4];
        #pragma unroll
        for (int mb = 0; mb < 2; mb++)
            #pragma unroll
            for (int nb = 0; nb < 8; nb++)
                #pragma unroll
                for (int q = 0; q < 4; q++)
                    acc[mb][nb][q] = 0.0f;

        for (int s = 0; s < kchunks; s++) {
            const int k0g = s * 64;
            __syncthreads();   // previous compute done before smem overwrite

            // ---- A tile: 128 rows x 64 k fp32 -> bf16 hi/lo
            const float* aSrc = (k0g < Ksplit)
                ? (A0 + (size_t)mHalf * lda + k0g)
                : (A1 + (size_t)mHalf * lda + (k0g - Ksplit));
            #pragma unroll
            for (int i = 0; i < 8; i++) {
                const int idx = tid + i * 256;
                const int r = idx >> 4, c4 = (idx & 15) << 2;
                const float4 v = *(const float4*)(aSrc + (size_t)r * lda + c4);
                __nv_bfloat16 h0 = __float2bfloat16_rn(v.x);
                __nv_bfloat16 h1 = __float2bfloat16_rn(v.y);
                __nv_bfloat16 h2 = __float2bfloat16_rn(v.z);
                __nv_bfloat16 h3 = __float2bfloat16_rn(v.w);
                __nv_bfloat16 l0 = __float2bfloat16_rn(v.x - __bfloat162float(h0));
                __nv_bfloat16 l1 = __float2bfloat16_rn(v.y - __bfloat162float(h1));
                __nv_bfloat16 l2 = __float2bfloat16_rn(v.z - __bfloat162float(h2));
                __nv_bfloat16 l3 = __float2bfloat16_rn(v.w - __bfloat162float(h3));
                *(uint2*)(sAhi + r * 72 + c4) = make_uint2(pk_bf(h0, h1), pk_bf(h2, h3));
                *(uint2*)(sAlo + r * 72 + c4) = make_uint2(pk_bf(l0, l1), pk_bf(l2, l3));
            }
            // ---- B tile: 128 n-rows x 64 k (pre-converted bf16)
            #pragma unroll
            for (int i = 0; i < 4; i++) {
                const int idx = tid + i * 256;
                const int r = idx >> 3, c8 = (idx & 7) << 3;
                const uint4 vh = *(const uint4*)(Whi + (size_t)(nBase + r) * K + k0g + c8);
                const uint4 vl = *(const uint4*)(Wlo + (size_t)(nBase + r) * K + k0g + c8);
                *(uint4*)(sBhi + r * 72 + c8) = vh;
                *(uint4*)(sBlo + r * 72 + c8) = vl;
            }
            __syncthreads();

            // ---- compute: 4 k16-steps, warp tile 32(M) x 64(N)
            #pragma unroll
            for (int kk = 0; kk < 4; kk++) {
                const int kb = kk * 16;
                uint32_t ah[2][4], al[2][4];
                #pragma unroll
                for (int mb = 0; mb < 2; mb++) {
                    const int r0 = warpM * 32 + mb * 16 + g;
                    const __nv_bfloat16* ph = sAhi + r0 * 72 + kb + t * 2;
                    ah[mb][0] = *(const uint32_t*)(ph);
                    ah[mb][1] = *(const uint32_t*)(ph + 8 * 72);
                    ah[mb][2] = *(const uint32_t*)(ph + 8);
                    ah[mb][3] = *(const uint32_t*)(ph + 8 * 72 + 8);
                    const __nv_bfloat16* pl = sAlo + r0 * 72 + kb + t * 2;
                    al[mb][0] = *(const uint32_t*)(pl);
                    al[mb][1] = *(const uint32_t*)(pl + 8 * 72);
                    al[mb][2] = *(const uint32_t*)(pl + 8);
                    al[mb][3] = *(const uint32_t*)(pl + 8 * 72 + 8);
                }
                #pragma unroll
                for (int nb = 0; nb < 8; nb++) {
                    const int n0 = warpN * 64 + nb * 8 + g;
                    const __nv_bfloat16* pbh = sBhi + n0 * 72 + kb + t * 2;
                    const __nv_bfloat16* pbl = sBlo + n0 * 72 + kb + t * 2;
                    const uint32_t bh0 = *(const uint32_t*)(pbh);
                    const uint32_t bh1 = *(const uint32_t*)(pbh + 8);
                    const uint32_t bl0 = *(const uint32_t*)(pbl);
                    const uint32_t bl1 = *(const uint32_t*)(pbl + 8);
                    #pragma unroll
                    for (int mb = 0; mb < 2; mb++) {
                        mma_bf16_16816(acc[mb][nb], ah[mb], bh0, bh1);
                        mma_bf16_16816(acc[mb][nb], al[mb], bh0, bh1);
                        mma_bf16_16816(acc[mb][nb], ah[mb], bl0, bl1);
                    }
                }
            }
        }

        // ---- epilogue: bias + gelu, float2 stores per fragment row pair
        #pragma unroll
        for (int mb = 0; mb < 2; mb++) {
            #pragma unroll
            for (int nb = 0; nb < 8; nb++) {
                const int row0 = mHalf + warpM * 32 + mb * 16 + g;
                const int colL = warpN * 64 + nb * 8 + t * 2;   // within CTA tile
                const int col  = nBase + colL;
                float2 o0, o1;
                o0.x = gelu_exact(acc[mb][nb][0] + sBias[colL + 0]);
                o0.y = gelu_exact(acc[mb][nb][1] + sBias[colL + 1]);
                o1.x = gelu_exact(acc[mb][nb][2] + sBias[colL + 0]);
                o1.y = gelu_exact(acc[mb][nb][3] + sBias[colL + 1]);
                *(float2*)(C + (size_t)row0 * HH + col)       = o0;
                *(float2*)(C + (size_t)(row0 + 8) * HH + col) = o1;
            }
        }
    }
#endif
}

// ---------------------------------------------------------------------------
// Deterministic segment sum: cell1[b,t,:] = sum_{ids[b,l]==t} seq[b,l,:]
// ---------------------------------------------------------------------------
__global__ void __launch_bounds__(256)
segsum_kernel(const int* __restrict__ ids)
{
    __shared__ int s_ids[LL];
    const int t = blockIdx.x, b = blockIdx.y, tid = threadIdx.x;
    for (int i = tid; i < LL; i += 256) s_ids[i] = ids[b * LL + i];
    __syncthreads();

    float4 acc = make_float4(0.f, 0.f, 0.f, 0.f);
    const float4* base = reinterpret_cast<const float4*>(g_seq) + (size_t)b * LL * (HH / 4) + tid;
    for (int l = 0; l < LL; l++) {
        if (s_ids[l] == t) {
            const float4 v = base[(size_t)l * (HH / 4)];
            acc.x += v.x; acc.y += v.y; acc.z += v.z; acc.w += v.w;
        }
    }
    reinterpret_cast<float4*>(g_cell1)[((size_t)(b * TT + t)) * (HH / 4) + tid] = acc;
}

// ---------------------------------------------------------------------------
// Gather: out[b,l,:] = cell2[b, ids[b,l], :]
// ---------------------------------------------------------------------------
__global__ void __launch_bounds__(256)
gather_kernel(const int* __restrict__ ids, float* __restrict__ out)
{
    const int l = blockIdx.x, b = blockIdx.y, tid = threadIdx.x;
    const int t = ids[b * LL + l];
    const float4 v = reinterpret_cast<const float4*>(g_cell2)[((size_t)(b * TT + t)) * (HH / 4) + tid];
    reinterpret_cast<float4*>(out)[((size_t)(b * LL + l)) * (HH / 4) + tid] = v;
}

// ---------------------------------------------------------------------------
extern "C" void kernel_launch(void* const* d_in, const int* in_sizes, int n_in,
                              void* d_out, int out_size)
{
    const float* former = (const float*)d_in[0];
    const float* hidden = (const float*)d_in[1];
    const int*   ids    = (const int*)  d_in[2];
    const float* Wd     = (const float*)d_in[4];   // [2048, 1024]
    const float* bd     = (const float*)d_in[5];
    const float* Wr     = (const float*)d_in[6];   // [1024, 1024]
    const float* br     = (const float*)d_in[7];
    float* out = (float*)d_out;

    float *seq, *c1, *c2;
    __nv_bfloat16 *wdh, *wdl, *wrh, *wrl;
    cudaGetSymbolAddress((void**)&seq, g_seq);
    cudaGetSymbolAddress((void**)&c1,  g_cell1);
    cudaGetSymbolAddress((void**)&c2,  g_cell2);
    cudaGetSymbolAddress((void**)&wdh, g_WdT_hi);
    cudaGetSymbolAddress((void**)&wdl, g_WdT_lo);
    cudaGetSymbolAddress((void**)&wrh, g_WrT_hi);
    cudaGetSymbolAddress((void**)&wrl, g_WrT_lo);

    cudaFuncSetAttribute(gemm_tc, cudaFuncAttributeMaxDynamicSharedMemorySize, SMEM_TOTAL);

    // W transpose + split (Wd: K=2048,N=1024 ; Wr: K=1024,N=1024)
    wtrans<<<dim3(32, 64), 256>>>(Wd, 2 * HH, HH, wdh, wdl);
    wtrans<<<dim3(32, 32), 256>>>(Wr, HH, HH, wrh, wrl);

    // Stage 1: seq = gelu(concat(former,hidden) @ W_down + b_down)
    gemm_tc<<<dim3(HH / 128, M1 / 256), 256, SMEM_TOTAL>>>(
        former, hidden, HH, /*Ksplit=*/HH, /*K=*/2 * HH, /*kchunks=*/32,
        wdh, wdl, bd, seq);

    // Stage 2: deterministic segment sum
    segsum_kernel<<<dim3(TT, BB), 256>>>(ids);

    // Stage 3: cell2 = gelu(cell1 @ W_row + b_row)
    gemm_tc<<<dim3(HH / 128, M2 / 256), 256, SMEM_TOTAL>>>(
        c1, c1, HH, /*Ksplit=*/HH, /*K=*/HH, /*kchunks=*/16,
        wrh, wrl, br, c2);

    // Stage 4: gather
    gather_kernel<<<dim3(LL, BB), 256>>>(ids, out);
}

// round 10
// speedup vs baseline: 4.7975x; 1.3702x over previous
#include <cuda_runtime.h>
#include <cuda_bf16.h>
#include <math.h>
#include <stdint.h>

#define BB   8
#define LL   2048
#define HH   1024
#define TT   256
#define M1   (BB * LL)    // 16384
#define M2   (BB * TT)    // 2048

// tcgen05 is only legal in an arch-specific pass (sm_103a/100a). The bench
// lowers through base sm_103, so the fallback HMMA path is what actually runs.
#if defined(__CUDA_ARCH_FEAT_SM103_ALL) || defined(__CUDA_ARCH_FEAT_SM100_ALL) || \
    (defined(__CUDA_ARCH_SPECIFIC__) && (__CUDA_ARCH_SPECIFIC__ >= 1000))
#define HAS_TCGEN05 1
#else
#define HAS_TCGEN05 0
#endif

// ---------------- scratch (__device__ globals; no allocation allowed) -------
__device__ float g_seq[(size_t)M1 * HH];      // 64 MiB
__device__ float g_cell1[(size_t)M2 * HH];    //  8 MiB
__device__ float g_cell2[(size_t)M2 * HH];    //  8 MiB
__device__ __align__(16) __nv_bfloat16 g_WdT_hi[(size_t)HH * 2 * HH];  // [1024][2048]
__device__ __align__(16) __nv_bfloat16 g_WdT_lo[(size_t)HH * 2 * HH];
__device__ __align__(16) __nv_bfloat16 g_WrT_hi[(size_t)HH * HH];      // [1024][1024]
__device__ __align__(16) __nv_bfloat16 g_WrT_lo[(size_t)HH * HH];
__device__ int g_entries[BB * LL];            // token idx ordered by (t, l)
__device__ int g_offsets[BB * (TT + 1)];

// ---------------- shared helpers --------------------------------------------
__device__ __forceinline__ uint32_t smem_u32(const void* p) {
    uint32_t a;
    asm("{ .reg .u64 t; cvta.to.shared.u64 t, %1; cvt.u32.u64 %0, t; }" : "=r"(a) : "l"(p));
    return a;
}
__device__ __forceinline__ uint32_t pk_bf(__nv_bfloat16 a, __nv_bfloat16 b) {
    return (uint32_t)__bfloat16_as_ushort(a) | ((uint32_t)__bfloat16_as_ushort(b) << 16);
}
__device__ __forceinline__ float gelu_exact(float x) {
    return 0.5f * x * (1.0f + erff(x * 0.7071067811865475244f));
}
__device__ __forceinline__ void cp_async16(uint32_t dst, const void* src) {
    asm volatile("cp.async.cg.shared.global [%0], [%1], 16;" :: "r"(dst), "l"(src) : "memory");
}
__device__ __forceinline__ void cp_commit() { asm volatile("cp.async.commit_group;" ::: "memory"); }
__device__ __forceinline__ void cp_wait0()  { asm volatile("cp.async.wait_group 0;" ::: "memory"); }

#if HAS_TCGEN05
// ---------------- tcgen05 helpers (arch-specific pass only) -----------------
__device__ __forceinline__ uint32_t elect1() {
    uint32_t r;
    asm volatile("{ .reg .pred p; elect.sync _|p, 0xFFFFFFFF; selp.b32 %0, 1, 0, p; }" : "=r"(r));
    return r;
}
__device__ __forceinline__ void mbar_init(uint32_t a, uint32_t cnt) {
    asm volatile("mbarrier.init.shared.b64 [%0], %1;" :: "r"(a), "r"(cnt) : "memory");
}
__device__ __forceinline__ void mbar_wait(uint32_t a, uint32_t phase) {
    uint32_t done;
    asm volatile(
        "{\n\t.reg .pred p;\n\t"
        "mbarrier.try_wait.parity.acquire.cta.shared::cta.b64 p, [%1], %2;\n\t"
        "selp.b32 %0, 1, 0, p;\n\t}"
        : "=r"(done) : "r"(a), "r"(phase) : "memory");
    if (!done) {
        asm volatile(
            "{\n\t.reg .pred P1;\n\t"
            "WL_%=:\n\t"
            "mbarrier.try_wait.parity.acquire.cta.shared::cta.b64 P1, [%0], %1, 0x989680;\n\t"
            "@P1 bra.uni WD_%=;\n\t"
            "bra.uni WL_%=;\n\t"
            "WD_%=:\n\t}"
            :: "r"(a), "r"(phase) : "memory");
    }
}
__device__ __forceinline__ void tmem_alloc(uint32_t smem_dst, uint32_t ncols) {
    asm volatile("tcgen05.alloc.cta_group::1.sync.aligned.shared::cta.b32 [%0], %1;"
                 :: "r"(smem_dst), "r"(ncols) : "memory");
}
__device__ __forceinline__ void tmem_dealloc(uint32_t tmem, uint32_t ncols) {
    asm volatile("tcgen05.relinquish_alloc_permit.cta_group::1.sync.aligned;");
    asm volatile("tcgen05.dealloc.cta_group::1.sync.aligned.b32 %0, %1;" :: "r"(tmem), "r"(ncols));
}
__device__ __forceinline__ void tc_commit(uint32_t mbar) {
    asm volatile("tcgen05.commit.cta_group::1.mbarrier::arrive::one.shared::cluster.b64 [%0];"
                 :: "r"(mbar) : "memory");
}
__device__ __forceinline__ void fence_async_shared() {
    asm volatile("fence.proxy.async.shared::cta;" ::: "memory");
}
__device__ __forceinline__ void tc_fence_after() {
    asm volatile("tcgen05.fence::after_thread_sync;" ::: "memory");
}
__device__ __forceinline__ void mma_f16_ss(uint32_t d, uint64_t ad, uint64_t bd,
                                           uint32_t idesc, uint32_t en) {
    asm volatile(
        "{\n\t.reg .pred p;\n\tsetp.ne.u32 p, %4, 0;\n\t"
        "tcgen05.mma.cta_group::1.kind::f16 [%0], %1, %2, %3, {%5, %5, %5, %5}, p;\n\t}"
        :: "r"(d), "l"(ad), "l"(bd), "r"(idesc), "r"(en), "r"(0u) : "memory");
}
#define LDTM_X32(r, addr)                                                         \
    asm volatile("tcgen05.ld.sync.aligned.32x32b.x32.b32 "                        \
        "{%0,%1,%2,%3,%4,%5,%6,%7,%8,%9,%10,%11,%12,%13,%14,%15,"                 \
        "%16,%17,%18,%19,%20,%21,%22,%23,%24,%25,%26,%27,%28,%29,%30,%31}, [%32];"\
        : "=r"((r)[0]),"=r"((r)[1]),"=r"((r)[2]),"=r"((r)[3]),                    \
          "=r"((r)[4]),"=r"((r)[5]),"=r"((r)[6]),"=r"((r)[7]),                    \
          "=r"((r)[8]),"=r"((r)[9]),"=r"((r)[10]),"=r"((r)[11]),                  \
          "=r"((r)[12]),"=r"((r)[13]),"=r"((r)[14]),"=r"((r)[15]),                \
          "=r"((r)[16]),"=r"((r)[17]),"=r"((r)[18]),"=r"((r)[19]),                \
          "=r"((r)[20]),"=r"((r)[21]),"=r"((r)[22]),"=r"((r)[23]),                \
          "=r"((r)[24]),"=r"((r)[25]),"=r"((r)[26]),"=r"((r)[27]),                \
          "=r"((r)[28]),"=r"((r)[29]),"=r"((r)[30]),"=r"((r)[31])                 \
        : "r"(addr))
__device__ __forceinline__ void ldtm_wait() {
    asm volatile("tcgen05.wait::ld.sync.aligned;" ::: "memory");
}
__device__ __forceinline__ uint64_t make_desc_sw128(uint32_t addr) {
    const uint64_t base = (uint64_t(2) << 61) | (uint64_t(1) << 46) |
                          (uint64_t(64) << 32) | (uint64_t(1) << 16);
    return base | ((uint64_t)(addr >> 4) & 0x3FFF);
}
#define IDESC_BF16_M128_N128 0x08200490u
#else
// ---------------- fallback helper: classic bf16 tensor-core mma -------------
__device__ __forceinline__ void mma_bf16_16816(float* c, const uint32_t* a,
                                               uint32_t b0, uint32_t b1) {
    asm volatile(
        "mma.sync.aligned.m16n8k16.row.col.f32.bf16.bf16.f32 "
        "{%0,%1,%2,%3}, {%4,%5,%6,%7}, {%8,%9}, {%0,%1,%2,%3};"
        : "+f"(c[0]), "+f"(c[1]), "+f"(c[2]), "+f"(c[3])
        : "r"(a[0]), "r"(a[1]), "r"(a[2]), "r"(a[3]), "r"(b0), "r"(b1));
}
#endif

// ---------------------------------------------------------------------------
// W transpose + bf16 hi/lo split:  T[n][k] = split(W[k][n])
// ---------------------------------------------------------------------------
__global__ void __launch_bounds__(256)
wtrans(const float* __restrict__ W, int K, int N,
       __nv_bfloat16* __restrict__ Thi, __nv_bfloat16* __restrict__ Tlo)
{
    __shared__ float t[32][33];
    const int n0 = blockIdx.x * 32, k0 = blockIdx.y * 32;
    const int tx = threadIdx.x & 31, ty = threadIdx.x >> 5;
    #pragma unroll
    for (int i = ty; i < 32; i += 8)
        t[i][tx] = W[(size_t)(k0 + i) * N + n0 + tx];
    __syncthreads();
    #pragma unroll
    for (int i = ty; i < 32; i += 8) {
        float x = t[tx][i];
        __nv_bfloat16 h = __float2bfloat16_rn(x);
        __nv_bfloat16 l = __float2bfloat16_rn(x - __bfloat162float(h));
        size_t o = (size_t)(n0 + i) * K + k0 + tx;
        Thi[o] = h;
        Tlo[o] = l;
    }
}

// ---------------------------------------------------------------------------
// GEMM + bias + gelu:  C[m][n] = gelu( A[m][:] . Wt[n][:] + bias[n] )
// ---------------------------------------------------------------------------
#define STAGE_BYTES 98304
#define SMEM_TOTAL  (1024 + 1024 + 2 * STAGE_BYTES)

__global__ void __launch_bounds__(256, 1)
gemm_tc(const float* __restrict__ A0, const float* __restrict__ A1,
        int lda, int Ksplit, int K, int kchunks,
        const __nv_bfloat16* __restrict__ Whi, const __nv_bfloat16* __restrict__ Wlo,
        const float* __restrict__ bias, float* __restrict__ C)
{
#if HAS_TCGEN05
    extern __shared__ char smem_raw[];
    const uint32_t sbase = smem_u32(smem_raw);
    const uint32_t abase = (sbase + 1023u) & ~1023u;
    char* sm = smem_raw + (abase - sbase);

    const uint32_t tmem_ptr_a = abase;
    const uint32_t mbar[2]    = { abase + 8, abase + 16 };
    float* sBias              = (float*)(sm + 512);

    const int tid = threadIdx.x, wid = tid >> 5, lid = tid & 31;
    const int mBase = blockIdx.y * 256;
    const int nBase = blockIdx.x * 128;

    if (wid == 0) tmem_alloc(tmem_ptr_a, 256);
    if (tid == 0) { mbar_init(mbar[0], 1); mbar_init(mbar[1], 1); }
    if (tid < 128) sBias[tid] = bias[nBase + tid];
    __syncthreads();

    uint32_t tmem_base;
    asm volatile("ld.shared.b32 %0, [%1];" : "=r"(tmem_base) : "r"(tmem_ptr_a));

    const int aCol = tid & 15, aRow0 = tid >> 4;
    const int bCol = tid & 7,  bRow0 = tid >> 3;

    for (int s = 0; s < kchunks; s++) {
        const int slot = s & 1;
        if (s >= 2) mbar_wait(mbar[slot], ((s - 2) >> 1) & 1);

        char* st   = sm + 1024 + slot * STAGE_BYTES;
        char* sAhi = st;
        char* sAlo = st + 32768;
        char* sBhi = st + 65536;
        char* sBlo = st + 81920;
        const int k0 = s * 64;

        const float* aSrc = (k0 < Ksplit)
            ? (A0 + (size_t)mBase * lda + k0)
            : (A1 + (size_t)mBase * lda + (k0 - Ksplit));
        #pragma unroll
        for (int i = 0; i < 16; i++) {
            const int r = aRow0 + (i << 4);
            const float4 v = *(const float4*)(aSrc + (size_t)r * lda + (aCol << 2));
            __nv_bfloat16 h0 = __float2bfloat16_rn(v.x);
            __nv_bfloat16 h1 = __float2bfloat16_rn(v.y);
            __nv_bfloat16 h2 = __float2bfloat16_rn(v.z);
            __nv_bfloat16 h3 = __float2bfloat16_rn(v.w);
            __nv_bfloat16 l0 = __float2bfloat16_rn(v.x - __bfloat162float(h0));
            __nv_bfloat16 l1 = __float2bfloat16_rn(v.y - __bfloat162float(h1));
            __nv_bfloat16 l2 = __float2bfloat16_rn(v.z - __bfloat162float(h2));
            __nv_bfloat16 l3 = __float2bfloat16_rn(v.w - __bfloat162float(h3));
            uint32_t off = (r << 7) + (aCol << 3);
            uint32_t sw  = off ^ ((off >> 3) & 0x70);
            *(uint2*)(sAhi + sw) = make_uint2(pk_bf(h0, h1), pk_bf(h2, h3));
            *(uint2*)(sAlo + sw) = make_uint2(pk_bf(l0, l1), pk_bf(l2, l3));
        }
        const __nv_bfloat16* bh = Whi + (size_t)nBase * K + k0;
        const __nv_bfloat16* bl = Wlo + (size_t)nBase * K + k0;
        #pragma unroll
        for (int i = 0; i < 4; i++) {
            const int r = bRow0 + (i << 5);
            const uint4 vh = *(const uint4*)(bh + (size_t)r * K + (bCol << 3));
            const uint4 vl = *(const uint4*)(bl + (size_t)r * K + (bCol << 3));
            uint32_t off = (r << 7) + (bCol << 4);
            uint32_t sw  = off ^ ((off >> 3) & 0x70);
            *(uint4*)(sBhi + sw) = vh;
            *(uint4*)(sBlo + sw) = vl;
        }
        fence_async_shared();
        __syncthreads();

        if (wid == 0 && elect1()) {
            const uint32_t stU = abase + 1024 + slot * STAGE_BYTES;
            const uint64_t bdh = make_desc_sw128(stU + 65536);
            const uint64_t bdl = make_desc_sw128(stU + 81920);
            #pragma unroll
            for (int sub = 0; sub < 2; sub++) {
                const uint32_t d   = tmem_base + sub * 128;
                const uint64_t adh = make_desc_sw128(stU + sub * 16384);
                const uint64_t adl = make_desc_sw128(stU + 32768 + sub * 16384);
                #pragma unroll
                for (int ks = 0; ks < 4; ks++)
                    mma_f16_ss(d, adh + 2 * ks, bdh + 2 * ks, IDESC_BF16_M128_N128,
                               (s == 0 && ks == 0) ? 0u : 1u);
                #pragma unroll
                for (int ks = 0; ks < 4; ks++)
                    mma_f16_ss(d, adl + 2 * ks, bdh + 2 * ks, IDESC_BF16_M128_N128, 1u);
                #pragma unroll
                for (int ks = 0; ks < 4; ks++)
                    mma_f16_ss(d, adh + 2 * ks, bdl + 2 * ks, IDESC_BF16_M128_N128, 1u);
            }
            tc_commit(mbar[slot]);
        }
    }

    {
        const int s2 = kchunks - 2, s1 = kchunks - 1;
        mbar_wait(mbar[s2 & 1], (s2 >> 1) & 1);
        mbar_wait(mbar[s1 & 1], (s1 >> 1) & 1);
    }
    tc_fence_after();

    {
        const int wg = wid >> 2, wsub = wid & 3;
        const int m = mBase + wg * 128 + wsub * 32 + lid;
        const uint32_t dbase = tmem_base + wg * 128;
        #pragma unroll
        for (int cb = 0; cb < 4; cb++) {
            uint32_t regs[32];
            LDTM_X32(regs, dbase + cb * 32);
            ldtm_wait();
            float* crow = C + (size_t)m * HH + nBase + cb * 32;
            #pragma unroll
            for (int j = 0; j < 32; j += 4) {
                float4 o;
                o.x = gelu_exact(__uint_as_float(regs[j + 0]) + sBias[cb * 32 + j + 0]);
                o.y = gelu_exact(__uint_as_float(regs[j + 1]) + sBias[cb * 32 + j + 1]);
                o.z = gelu_exact(__uint_as_float(regs[j + 2]) + sBias[cb * 32 + j + 2]);
                o.w = gelu_exact(__uint_as_float(regs[j + 3]) + sBias[cb * 32 + j + 3]);
                *(float4*)(crow + j) = o;
            }
        }
    }
    __syncthreads();
    if (wid == 0) tmem_dealloc(tmem_base, 256);

#else  // ============ mma.sync bf16 fallback, double-buffered ===============
    // SMEM per stage: Ahi/Alo/Bhi/Blo, each 128 rows x 72 bf16 (144 B stride).
    extern __shared__ char smem_raw[];
    float* sBias = (float*)(smem_raw);
    char* sm = smem_raw + 1024;
    const uint32_t smU = smem_u32(sm);
    constexpr int ROWB  = 144;                 // 72 bf16
    constexpr int ABUF  = 128 * ROWB;          // 18432
    constexpr int STAGE = 4 * ABUF;            // 73728

    const int tid = threadIdx.x, wid = tid >> 5, lane = tid & 31;
    const int mBase = blockIdx.y * 256;
    const int nBase = blockIdx.x * 128;
    const int g = lane >> 2, t = lane & 3;
    const int warpM = wid >> 1, warpN = wid & 1;     // 4 (M) x 2 (N) warps
    const int aRowB = tid >> 4, aCol4 = (tid & 15) << 2;   // A ld map
    const int bRowB = tid >> 3, bCol8 = (tid & 7) << 3;    // B cp map

    if (tid < 128) sBias[tid] = bias[nBase + tid];

    for (int half = 0; half < 2; half++) {
        const int mHalf = mBase + half * 128;
        float acc[2][8][4];
        #pragma unroll
        for (int mb = 0; mb < 2; mb++)
            #pragma unroll
            for (int nb = 0; nb < 8; nb++)
                #pragma unroll
                for (int q = 0; q < 4; q++)
                    acc[mb][nb][q] = 0.0f;

        float4 aPre[8];

        // ---- helpers as lambdas
        auto issue_b = [&](int stage, int k0g) {
            const uint32_t sb = smU + stage * STAGE;
            #pragma unroll
            for (int i = 0; i < 4; i++) {
                const int r = bRowB + (i << 5);
                const uint32_t o = r * ROWB + bCol8 * 2;
                cp_async16(sb + 2 * ABUF + o, Whi + (size_t)(nBase + r) * K + k0g + bCol8);
                cp_async16(sb + 3 * ABUF + o, Wlo + (size_t)(nBase + r) * K + k0g + bCol8);
            }
            cp_commit();
        };
        auto load_a = [&](int k0g) {
            const float* aSrc = (k0g < Ksplit)
                ? (A0 + (size_t)mHalf * lda + k0g)
                : (A1 + (size_t)mHalf * lda + (k0g - Ksplit));
            #pragma unroll
            for (int i = 0; i < 8; i++) {
                const int r = aRowB + (i << 4);
                aPre[i] = *(const float4*)(aSrc + (size_t)r * lda + aCol4);
            }
        };
        auto store_a = [&](int stage) {
            char* sb = sm + stage * STAGE;
            #pragma unroll
            for (int i = 0; i < 8; i++) {
                const int r = aRowB + (i << 4);
                const float4 v = aPre[i];
                __nv_bfloat16 h0 = __float2bfloat16_rn(v.x);
                __nv_bfloat16 h1 = __float2bfloat16_rn(v.y);
                __nv_bfloat16 h2 = __float2bfloat16_rn(v.z);
                __nv_bfloat16 h3 = __float2bfloat16_rn(v.w);
                __nv_bfloat16 l0 = __float2bfloat16_rn(v.x - __bfloat162float(h0));
                __nv_bfloat16 l1 = __float2bfloat16_rn(v.y - __bfloat162float(h1));
                __nv_bfloat16 l2 = __float2bfloat16_rn(v.z - __bfloat162float(h2));
                __nv_bfloat16 l3 = __float2bfloat16_rn(v.w - __bfloat162float(h3));
                const uint32_t o = r * ROWB + aCol4 * 2;
                *(uint2*)(sb + o)        = make_uint2(pk_bf(h0, h1), pk_bf(h2, h3));
                *(uint2*)(sb + ABUF + o) = make_uint2(pk_bf(l0, l1), pk_bf(l2, l3));
            }
        };

        // ---- prologue: stage chunk 0 into buffer 0
        issue_b(0, 0);
        load_a(0);
        store_a(0);
        cp_wait0();
        __syncthreads();

        for (int s = 0; s < kchunks; s++) {
            const int st = s & 1, nx = st ^ 1;
            if (s + 1 < kchunks) {
                issue_b(nx, (s + 1) * 64);
                load_a((s + 1) * 64);
            }

            // ---- compute chunk s from stage st
            const __nv_bfloat16* sAhi = (const __nv_bfloat16*)(sm + st * STAGE);
            const __nv_bfloat16* sAlo = (const __nv_bfloat16*)(sm + st * STAGE + ABUF);
            const __nv_bfloat16* sBhi = (const __nv_bfloat16*)(sm + st * STAGE + 2 * ABUF);
            const __nv_bfloat16* sBlo = (const __nv_bfloat16*)(sm + st * STAGE + 3 * ABUF);
            #pragma unroll
            for (int kk = 0; kk < 4; kk++) {
                const int kb = kk * 16;
                uint32_t ah[2][4], al[2][4];
                #pragma unroll
                for (int mb = 0; mb < 2; mb++) {
                    const int r0 = warpM * 32 + mb * 16 + g;
                    const __nv_bfloat16* ph = sAhi + r0 * 72 + kb + t * 2;
                    ah[mb][0] = *(const uint32_t*)(ph);
                    ah[mb][1] = *(const uint32_t*)(ph + 8 * 72);
                    ah[mb][2] = *(const uint32_t*)(ph + 8);
                    ah[mb][3] = *(const uint32_t*)(ph + 8 * 72 + 8);
                    const __nv_bfloat16* pl = sAlo + r0 * 72 + kb + t * 2;
                    al[mb][0] = *(const uint32_t*)(pl);
                    al[mb][1] = *(const uint32_t*)(pl + 8 * 72);
                    al[mb][2] = *(const uint32_t*)(pl + 8);
                    al[mb][3] = *(const uint32_t*)(pl + 8 * 72 + 8);
                }
                #pragma unroll
                for (int nb = 0; nb < 8; nb++) {
                    const int n0 = warpN * 64 + nb * 8 + g;
                    const __nv_bfloat16* pbh = sBhi + n0 * 72 + kb + t * 2;
                    const __nv_bfloat16* pbl = sBlo + n0 * 72 + kb + t * 2;
                    const uint32_t bh0 = *(const uint32_t*)(pbh);
                    const uint32_t bh1 = *(const uint32_t*)(pbh + 8);
                    const uint32_t bl0 = *(const uint32_t*)(pbl);
                    const uint32_t bl1 = *(const uint32_t*)(pbl + 8);
                    #pragma unroll
                    for (int mb = 0; mb < 2; mb++) {
                        mma_bf16_16816(acc[mb][nb], ah[mb], bh0, bh1);
                        mma_bf16_16816(acc[mb][nb], al[mb], bh0, bh1);
                        mma_bf16_16816(acc[mb][nb], ah[mb], bl0, bl1);
                    }
                }
            }

            if (s + 1 < kchunks) {
                store_a(nx);
                cp_wait0();
            }
            __syncthreads();
        }

        // ---- epilogue: bias + gelu
        #pragma unroll
        for (int mb = 0; mb < 2; mb++) {
            #pragma unroll
            for (int nb = 0; nb < 8; nb++) {
                const int row0 = mHalf + warpM * 32 + mb * 16 + g;
                const int colL = warpN * 64 + nb * 8 + t * 2;
                const int col  = nBase + colL;
                float2 o0, o1;
                o0.x = gelu_exact(acc[mb][nb][0] + sBias[colL + 0]);
                o0.y = gelu_exact(acc[mb][nb][1] + sBias[colL + 1]);
                o1.x = gelu_exact(acc[mb][nb][2] + sBias[colL + 0]);
                o1.y = gelu_exact(acc[mb][nb][3] + sBias[colL + 1]);
                *(float2*)(C + (size_t)row0 * HH + col)       = o0;
                *(float2*)(C + (size_t)(row0 + 8) * HH + col) = o1;
            }
        }
    }
#endif
}

// ---------------------------------------------------------------------------
// Bucket build: deterministic per-(b,t) index lists, ordered by ascending l.
// One block per batch. All-integer -> bitwise deterministic.
// ---------------------------------------------------------------------------
__global__ void __launch_bounds__(256)
bucket_build(const int* __restrict__ ids)
{
    __shared__ int s_ids[LL];
    __shared__ int s_ofs[TT + 1];
    const int b = blockIdx.x, tid = threadIdx.x;

    for (int i = tid; i < LL; i += 256) s_ids[i] = ids[b * LL + i];
    for (int i = tid; i <= TT; i += 256) s_ofs[i] = 0;
    __syncthreads();
    for (int i = tid; i < LL; i += 256) atomicAdd(&s_ofs[s_ids[i] + 1], 1);
    __syncthreads();
    if (tid == 0) {
        int run = 0;
        #pragma unroll 4
        for (int i = 1; i <= TT; i++) { run += s_ofs[i]; s_ofs[i] = run; }
    }
    __syncthreads();
    for (int i = tid; i <= TT; i += 256) g_offsets[b * (TT + 1) + i] = s_ofs[i];

    // thread tid owns cell tid: scan ids in order, place matches
    int ofs = s_ofs[tid];
    for (int l = 0; l < LL; l++)
        if (s_ids[l] == tid) g_entries[b * LL + ofs++] = l;
}

// ---------------------------------------------------------------------------
// Segment-sum apply: each (t, b) block sums only its own rows (list order).
// ---------------------------------------------------------------------------
__global__ void __launch_bounds__(256)
segsum_apply()
{
    const int t = blockIdx.x, b = blockIdx.y, tid = threadIdx.x;
    const int start = g_offsets[b * (TT + 1) + t];
    const int end   = g_offsets[b * (TT + 1) + t + 1];
    const float4* base = reinterpret_cast<const float4*>(g_seq) + (size_t)b * LL * (HH / 4) + tid;

    float4 acc = make_float4(0.f, 0.f, 0.f, 0.f);
    for (int i = start; i < end; i++) {
        const int l = __ldg(&g_entries[b * LL + i]);
        const float4 v = base[(size_t)l * (HH / 4)];
        acc.x += v.x; acc.y += v.y; acc.z += v.z; acc.w += v.w;
    }
    reinterpret_cast<float4*>(g_cell1)[((size_t)(b * TT + t)) * (HH / 4) + tid] = acc;
}

// ---------------------------------------------------------------------------
// Gather: out[b,l,:] = cell2[b, ids[b,l], :]
// ---------------------------------------------------------------------------
__global__ void __launch_bounds__(256)
gather_kernel(const int* __restrict__ ids, float* __restrict__ out)
{
    const int l = blockIdx.x, b = blockIdx.y, tid = threadIdx.x;
    const int t = ids[b * LL + l];
    const float4 v = reinterpret_cast<const float4*>(g_cell2)[((size_t)(b * TT + t)) * (HH / 4) + tid];
    reinterpret_cast<float4*>(out)[((size_t)(b * LL + l)) * (HH / 4) + tid] = v;
}

// ---------------------------------------------------------------------------
extern "C" void kernel_launch(void* const* d_in, const int* in_sizes, int n_in,
                              void* d_out, int out_size)
{
    const float* former = (const float*)d_in[0];
    const float* hidden = (const float*)d_in[1];
    const int*   ids    = (const int*)  d_in[2];
    const float* Wd     = (const float*)d_in[4];   // [2048, 1024]
    const float* bd     = (const float*)d_in[5];
    const float* Wr     = (const float*)d_in[6];   // [1024, 1024]
    const float* br     = (const float*)d_in[7];
    float* out = (float*)d_out;

    float *seq, *c1, *c2;
    __nv_bfloat16 *wdh, *wdl, *wrh, *wrl;
    cudaGetSymbolAddress((void**)&seq, g_seq);
    cudaGetSymbolAddress((void**)&c1,  g_cell1);
    cudaGetSymbolAddress((void**)&c2,  g_cell2);
    cudaGetSymbolAddress((void**)&wdh, g_WdT_hi);
    cudaGetSymbolAddress((void**)&wdl, g_WdT_lo);
    cudaGetSymbolAddress((void**)&wrh, g_WrT_hi);
    cudaGetSymbolAddress((void**)&wrl, g_WrT_lo);

    cudaFuncSetAttribute(gemm_tc, cudaFuncAttributeMaxDynamicSharedMemorySize, SMEM_TOTAL);

    // W transpose + split, and bucket lists (independent of GEMM1)
    wtrans<<<dim3(32, 64), 256>>>(Wd, 2 * HH, HH, wdh, wdl);
    wtrans<<<dim3(32, 32), 256>>>(Wr, HH, HH, wrh, wrl);
    bucket_build<<<BB, 256>>>(ids);

    // Stage 1: seq = gelu(concat(former,hidden) @ W_down + b_down)
    gemm_tc<<<dim3(HH / 128, M1 / 256), 256, SMEM_TOTAL>>>(
        former, hidden, HH, /*Ksplit=*/HH, /*K=*/2 * HH, /*kchunks=*/32,
        wdh, wdl, bd, seq);

    // Stage 2: segment sum via per-cell lists
    segsum_apply<<<dim3(TT, BB), 256>>>();

    // Stage 3: cell2 = gelu(cell1 @ W_row + b_row)
    gemm_tc<<<dim3(HH / 128, M2 / 256), 256, SMEM_TOTAL>>>(
        c1, c1, HH, /*Ksplit=*/HH, /*K=*/HH, /*kchunks=*/16,
        wrh, wrl, br, c2);

    // Stage 4: gather
    gather_kernel<<<dim3(LL, BB), 256>>>(ids, out);
}